// round 2
// baseline (speedup 1.0000x reference)
#include <cuda_runtime.h>
#include <cstdint>
#include <cstddef>

#define C_   32
#define H_   192
#define W_   256
#define S_   9
#define G_   8
#define HW_  (H_*W_)          // 49152
#define PIX  64               // pixels per block
#define NTHR 64
#define TILE_F  (PIX*S_)      // 576 floats per channel sub-tile
#define TILE_F4 (TILE_F/4)    // 144 float4
#define MACRO_F4 (4*TILE_F4)  // 576 float4 per 4-channel macro tile (9216 B)
#define NTILE 79              // 8 phase-1 + 8 (g=7 src) + 7*9 (g=6..0)

__device__ float g_M[C_*C_];  // Wp^T Wp
__device__ float g_v[C_];     // Wp^T bp

__global__ void gcfs_setup(const float* __restrict__ Wp, const float* __restrict__ bp) {
    int t = threadIdx.x;
    for (int e = t; e < C_*C_; e += blockDim.x) {
        int i = e >> 5, j = e & 31;
        float m = 0.f;
        #pragma unroll
        for (int d = 0; d < C_; d++) m += Wp[d*C_ + i] * Wp[d*C_ + j];
        g_M[e] = m;
    }
    if (t < C_) {
        float v = 0.f;
        #pragma unroll
        for (int d = 0; d < C_; d++) v += bp[d] * Wp[d*C_ + t];
        g_v[t] = v;
    }
}

__device__ __forceinline__ void cp16(void* smem, const void* g) {
    uint32_t sa = (uint32_t)__cvta_generic_to_shared(smem);
    asm volatile("cp.async.cg.shared.global [%0], [%1], 16;\n" :: "r"(sa), "l"(g) : "memory");
}
__device__ __forceinline__ void cp_commit() {
    asm volatile("cp.async.commit_group;\n" ::: "memory");
}
template<int NW> __device__ __forceinline__ void cp_wait() {
    asm volatile("cp.async.wait_group %0;\n" :: "n"(NW) : "memory");
}

// tile j -> (image n, channel base cb)
// j in [0,8):   ref group j                (phase 1)
// j in [8,16):  src n=j-7, group 7         (g=7 refg captured from phase-1 tile 7)
// j in [16,79): k2=j-16; g=6-k2/9; r=k2%9; r==0 -> ref group g, else src n=r group g
__device__ __forceinline__ void tdesc(int j, int& n, int& cb) {
    if (j < 8)       { n = 0;      cb = 4*j; }
    else if (j < 16) { n = j - 7;  cb = 28;  }
    else {
        int k2 = j - 16;
        int q  = k2 / 9;
        int r  = k2 - 9*q;
        n  = (r == 0) ? 0 : r;
        cb = 4*(6 - q);
    }
}

__global__ __launch_bounds__(NTHR, 5)
void gcfs_main(const float* __restrict__ f, float* __restrict__ out) {
    __shared__ float  sM[C_*C_];
    __shared__ float  sv[C_];
    __shared__ float4 sbuf[4][MACRO_F4];   // 4 x 9216 B, prefetch distance 3

    const int tid  = threadIdx.x;
    const int pix0 = blockIdx.x * PIX;
    const int p    = pix0 + tid;

    for (int e = tid; e < C_*C_; e += NTHR) sM[e] = g_M[e];
    if (tid < C_) sv[tid] = g_v[tid];

    auto stage = [&](int j, float4* dst) {
        int n, cb; tdesc(j, n, cb);
        #pragma unroll
        for (int k = 0; k < 9; k++) {
            int idx = tid + k*NTHR;              // 0..575
            int sub = idx / TILE_F4;             // channel 0..3
            int off = idx - sub*TILE_F4;         // float4 within channel tile
            const float* gsrc = f + ((size_t)(n*C_ + cb + sub)*HW_ + pix0)*S_ + (size_t)off*4;
            cp16(dst + idx, gsrc);
        }
        cp_commit();
    };

    // center-tap reference vector r_mid
    float rm[C_];
    #pragma unroll
    for (int c = 0; c < C_; c++)
        rm[c] = __ldg(f + ((size_t)c*HW_ + p)*S_ + (S_/2));

    float logit[S_];
    #pragma unroll
    for (int s = 0; s < S_; s++) logit[s] = 0.f;
    float att[S_];
    float refg[4][S_];

    __syncthreads();  // sM/sv visible

    // pipeline prologue: tiles 0,1,2 in flight
    stage(0, sbuf[0]);
    stage(1, sbuf[1]);
    stage(2, sbuf[2]);

    for (int j = 0; j < NTILE; j++) {
        if (j + 3 < NTILE) { stage(j + 3, sbuf[(j + 3) & 3]); cp_wait<3>(); }
        else if (j + 2 < NTILE) cp_wait<2>();
        else if (j + 1 < NTILE) cp_wait<1>();
        else                    cp_wait<0>();
        __syncthreads();                          // tile j visible to all threads

        const float* tile = (const float*)sbuf[j & 3];

        if (j < 8) {
            // ---- phase 1: logits ----
            #pragma unroll
            for (int c4 = 0; c4 < 4; c4++) {
                int c = 4*j + c4;
                float t = sv[c];
                #pragma unroll
                for (int d = 0; d < C_; d++)
                    t = fmaf(rm[d], sM[d*C_ + c], t);
                const float* row = tile + c4*TILE_F + tid*S_;
                #pragma unroll
                for (int s = 0; s < S_; s++) {
                    float rv = row[s];
                    logit[s] = fmaf(t, rv, logit[s]);
                    if (j == 7) refg[c4][s] = rv;  // capture ref group 7 for free
                }
            }
        } else {
            if (j == 8) {
                // ---- softmax (once) ----
                const float scale = 0.17677669529663689f;  // 1/sqrt(32)
                float mx = -1e30f;
                #pragma unroll
                for (int s = 0; s < S_; s++) { logit[s] *= scale; mx = fmaxf(mx, logit[s]); }
                float sum = 0.f;
                #pragma unroll
                for (int s = 0; s < S_; s++) { att[s] = __expf(logit[s] - mx); sum += att[s]; }
                float invs = 1.0f / sum;
                #pragma unroll
                for (int s = 0; s < S_; s++) att[s] *= invs;
            }
            int n, g;
            bool is_ref;
            if (j < 16) { n = j - 7; g = 7; is_ref = false; }
            else {
                int k2 = j - 16;
                int q  = k2 / 9;
                int r  = k2 - 9*q;
                g = 6 - q; n = r; is_ref = (r == 0);
            }
            if (is_ref) {
                #pragma unroll
                for (int c4 = 0; c4 < 4; c4++) {
                    const float* row = tile + c4*TILE_F + tid*S_;
                    #pragma unroll
                    for (int s = 0; s < S_; s++) refg[c4][s] = row[s];
                }
            } else {
                float acc[S_];
                #pragma unroll
                for (int s = 0; s < S_; s++) acc[s] = 0.f;
                #pragma unroll
                for (int c4 = 0; c4 < 4; c4++) {
                    const float* row = tile + c4*TILE_F + tid*S_;
                    #pragma unroll
                    for (int s = 0; s < S_; s++)
                        acc[s] = fmaf(refg[c4][s], row[s], acc[s]);
                }
                float o = 0.f;
                #pragma unroll
                for (int s = 0; s < S_; s++) o = fmaf(acc[s], att[s], o);
                out[(size_t)((n - 1)*G_ + g)*HW_ + p] = o;
            }
        }
        __syncthreads();   // all reads of buffer (j&3) done before it is restaged
    }
}

extern "C" void kernel_launch(void* const* d_in, const int* in_sizes, int n_in,
                              void* d_out, int out_size) {
    const float* f  = (const float*)d_in[0];
    const float* Wp = (const float*)d_in[1];
    const float* bp = (const float*)d_in[2];

    gcfs_setup<<<1, 256>>>(Wp, bp);
    gcfs_main<<<HW_/PIX, NTHR>>>(f, (float*)d_out);
}

// round 4
// speedup vs baseline: 2.2340x; 2.2340x over previous
#include <cuda_runtime.h>
#include <cstdint>
#include <cstddef>

#define C_   32
#define H_   192
#define W_   256
#define S_   9
#define G_   8
#define HW_  (H_*W_)          // 49152
#define PIX  128              // pixels per block
#define NTHR 128
#define TILE_F  (PIX*S_)      // 1152 floats per channel sub-tile
#define TILE_F4 (TILE_F/4)    // 288 float4
#define MACRO_F4 (4*TILE_F4)  // 1152 float4 per macro tile (18432 B)
#define NTILE 80              // 8 phase-1 + 72 phase-2

__device__ float g_M[C_*C_];  // Wp^T Wp
__device__ float g_v[C_];     // Wp^T bp

__global__ void gcfs_setup(const float* __restrict__ Wp, const float* __restrict__ bp) {
    int t = threadIdx.x;
    for (int e = t; e < C_*C_; e += blockDim.x) {
        int i = e >> 5, j = e & 31;
        float m = 0.f;
        #pragma unroll
        for (int d = 0; d < C_; d++) m += Wp[d*C_ + i] * Wp[d*C_ + j];
        g_M[e] = m;
    }
    if (t < C_) {
        float v = 0.f;
        #pragma unroll
        for (int d = 0; d < C_; d++) v += bp[d] * Wp[d*C_ + t];
        g_v[t] = v;
    }
}

__device__ __forceinline__ void cp16(void* smem, const void* g) {
    uint32_t sa = (uint32_t)__cvta_generic_to_shared(smem);
    asm volatile("cp.async.cg.shared.global [%0], [%1], 16;\n" :: "r"(sa), "l"(g) : "memory");
}
__device__ __forceinline__ void cp_commit() {
    asm volatile("cp.async.commit_group;\n" ::: "memory");
}
template<int NW> __device__ __forceinline__ void cp_wait() {
    asm volatile("cp.async.wait_group %0;\n" :: "n"(NW) : "memory");
}

// unified tile map (IDENTICAL order to round-1's two phases):
// j in [0,8):  ref group j                      (phase 1)
// j >= 8:      k=j-8; g=k/9; r=k%9;
//              r==0 -> ref group g (refg reload), else src n=r, group g
__device__ __forceinline__ void tdesc(int j, int& n, int& cb) {
    if (j < 8) { n = 0; cb = 4*j; }
    else {
        int k = j - 8;
        int g = k / 9;
        int r = k - 9*g;
        n  = (r == 0) ? 0 : r;
        cb = 4*g;
    }
}

__global__ __launch_bounds__(NTHR)
void gcfs_main(const float* __restrict__ f, float* __restrict__ out) {
    __shared__ float  sM[C_*C_];
    __shared__ float  sv[C_];
    __shared__ float4 sbuf[3][MACRO_F4];   // 3 x 18432 B, prefetch distance 2

    const int tid  = threadIdx.x;
    const int pix0 = blockIdx.x * PIX;
    const int p    = pix0 + tid;

    for (int e = tid; e < C_*C_; e += NTHR) sM[e] = g_M[e];
    if (tid < C_) sv[tid] = g_v[tid];

    auto stage = [&](int j, float4* dst) {
        int n, cb; tdesc(j, n, cb);
        #pragma unroll
        for (int k = 0; k < 9; k++) {
            int idx = tid + k*NTHR;              // 0..1151
            int sub = idx / TILE_F4;             // channel 0..3
            int off = idx - sub*TILE_F4;         // float4 within channel tile
            const float* gsrc = f + ((size_t)(n*C_ + cb + sub)*HW_ + pix0)*S_ + (size_t)off*4;
            cp16(dst + idx, gsrc);
        }
        cp_commit();
    };

    // center-tap reference vector r_mid
    float rm[C_];
    #pragma unroll
    for (int c = 0; c < C_; c++)
        rm[c] = __ldg(f + ((size_t)c*HW_ + p)*S_ + (S_/2));

    float logit[S_];
    #pragma unroll
    for (int s = 0; s < S_; s++) logit[s] = 0.f;
    float att[S_];
    float refg[4][S_];

    __syncthreads();  // sM/sv visible

    // prologue: tiles 0,1 in flight
    stage(0, sbuf[0]);
    stage(1, sbuf[1]);

    for (int j = 0; j < NTILE; j++) {
        if (j + 2 < NTILE) { stage(j + 2, sbuf[(j + 2) % 3]); cp_wait<2>(); }
        else if (j + 1 < NTILE) cp_wait<1>();
        else                    cp_wait<0>();
        __syncthreads();                          // tile j visible to all threads

        const float* tile = (const float*)sbuf[j % 3];

        if (j < 8) {
            // ---- phase 1: logits over ref ----
            #pragma unroll
            for (int c4 = 0; c4 < 4; c4++) {
                int c = 4*j + c4;
                float t = sv[c];
                #pragma unroll
                for (int d = 0; d < C_; d++)
                    t = fmaf(rm[d], sM[d*C_ + c], t);   // M symmetric; broadcast smem reads
                const float* row = tile + c4*TILE_F + tid*S_;
                #pragma unroll
                for (int s = 0; s < S_; s++)
                    logit[s] = fmaf(t, row[s], logit[s]);
            }
        } else {
            if (j == 8) {
                // ---- softmax (once) ----
                const float scale = 0.17677669529663689f;  // 1/sqrt(32)
                float mx = -1e30f;
                #pragma unroll
                for (int s = 0; s < S_; s++) { logit[s] *= scale; mx = fmaxf(mx, logit[s]); }
                float sum = 0.f;
                #pragma unroll
                for (int s = 0; s < S_; s++) { att[s] = __expf(logit[s] - mx); sum += att[s]; }
                float invs = 1.0f / sum;
                #pragma unroll
                for (int s = 0; s < S_; s++) att[s] *= invs;
            }
            int k = j - 8;
            int g = k / 9;
            int r = k - 9*g;
            if (r == 0) {
                // ref group g -> registers
                #pragma unroll
                for (int c4 = 0; c4 < 4; c4++) {
                    const float* row = tile + c4*TILE_F + tid*S_;
                    #pragma unroll
                    for (int s = 0; s < S_; s++) refg[c4][s] = row[s];
                }
            } else {
                float acc[S_];
                #pragma unroll
                for (int s = 0; s < S_; s++) acc[s] = 0.f;
                #pragma unroll
                for (int c4 = 0; c4 < 4; c4++) {
                    const float* row = tile + c4*TILE_F + tid*S_;
                    #pragma unroll
                    for (int s = 0; s < S_; s++)
                        acc[s] = fmaf(refg[c4][s], row[s], acc[s]);
                }
                float o = 0.f;
                #pragma unroll
                for (int s = 0; s < S_; s++) o = fmaf(acc[s], att[s], o);
                out[(size_t)((r - 1)*G_ + g)*HW_ + p] = o;
            }
        }
        __syncthreads();   // all reads of buffer (j%3) done before it is restaged
    }
}

extern "C" void kernel_launch(void* const* d_in, const int* in_sizes, int n_in,
                              void* d_out, int out_size) {
    const float* f  = (const float*)d_in[0];
    const float* Wp = (const float*)d_in[1];
    const float* bp = (const float*)d_in[2];

    gcfs_setup<<<1, 256>>>(Wp, bp);
    gcfs_main<<<HW_/PIX, NTHR>>>(f, (float*)d_out);
}

// round 6
// speedup vs baseline: 2.5736x; 1.1520x over previous
#include <cuda_runtime.h>
#include <cstdint>
#include <cstddef>

#define C_   32
#define H_   192
#define W_   256
#define S_   9
#define G_   8
#define HW_  (H_*W_)          // 49152
#define PIX  128              // pixels per block
#define NTHR 128
#define TILE_F  (PIX*S_)      // 1152 floats per channel sub-tile
#define TILE_F4 (TILE_F/4)    // 288 float4
#define MACRO_F4 (4*TILE_F4)  // 1152 float4 per macro tile (18432 B)
#define NBUF 4
#define SMEM_BYTES (NBUF*MACRO_F4*16)   // 73728
#define NTILE 79              // 8 phase-1 + 8 (g=7 src) + 7*9 (g=6..0)

__device__ __align__(16) float g_M[C_*C_];  // Wp^T Wp
__device__ __align__(16) float g_v[C_];     // Wp^T bp

__global__ void gcfs_setup(const float* __restrict__ Wp, const float* __restrict__ bp) {
    int t = threadIdx.x;
    for (int e = t; e < C_*C_; e += blockDim.x) {
        int i = e >> 5, j = e & 31;
        float m = 0.f;
        #pragma unroll
        for (int d = 0; d < C_; d++) m += Wp[d*C_ + i] * Wp[d*C_ + j];
        g_M[e] = m;
    }
    if (t < C_) {
        float v = 0.f;
        #pragma unroll
        for (int d = 0; d < C_; d++) v += bp[d] * Wp[d*C_ + t];
        g_v[t] = v;
    }
}

__device__ __forceinline__ void cp16(void* smem, const void* g) {
    uint32_t sa = (uint32_t)__cvta_generic_to_shared(smem);
    asm volatile("cp.async.cg.shared.global [%0], [%1], 16;\n" :: "r"(sa), "l"(g) : "memory");
}
__device__ __forceinline__ void cp_commit() {
    asm volatile("cp.async.commit_group;\n" ::: "memory");
}
template<int NW> __device__ __forceinline__ void cp_wait() {
    asm volatile("cp.async.wait_group %0;\n" :: "n"(NW) : "memory");
}

// tile map (verified in round 2):
// j in [0,8):   ref group j                 (phase 1; j==7 captures refg for g=7)
// j in [8,16):  src n=j-7, group 7
// j in [16,79): k2=j-16; q=k2/9; r=k2%9; g=6-q; r==0 -> ref group g, else src n=r group g
__device__ __forceinline__ void tdesc(int j, int& n, int& cb) {
    if (j < 8)       { n = 0;     cb = 4*j; }
    else if (j < 16) { n = j - 7; cb = 28;  }
    else {
        int k2 = j - 16;
        int q  = k2 / 9;
        int r  = k2 - 9*q;
        n  = (r == 0) ? 0 : r;
        cb = 4*(6 - q);
    }
}

__global__ __launch_bounds__(NTHR, 3)
void gcfs_main(const float* __restrict__ f, float* __restrict__ out) {
    extern __shared__ float4 sbuf[];   // NBUF x MACRO_F4, dynamic (73728 B)

    const int tid  = threadIdx.x;
    const int pix0 = blockIdx.x * PIX;
    const int p    = pix0 + tid;

    auto buf = [&](int i) { return sbuf + (size_t)i * MACRO_F4; };

    auto stage = [&](int j) {
        float4* dst = buf(j & (NBUF - 1));
        int n, cb; tdesc(j, n, cb);
        #pragma unroll
        for (int k = 0; k < 9; k++) {
            int idx = tid + k*NTHR;              // 0..1151
            int sub = idx / TILE_F4;             // channel 0..3
            int off = idx - sub*TILE_F4;         // float4 within channel tile
            const float* gsrc = f + ((size_t)(n*C_ + cb + sub)*HW_ + pix0)*S_ + (size_t)off*4;
            cp16(dst + idx, gsrc);
        }
        cp_commit();
    };

    // ---- prologue: stage [M|v] into buf3, then tiles 0 and 1 ----
    {
        float4* mv = buf(3);
        // g_M: 256 float4, g_v: 8 float4
        cp16(mv + tid,       (const float4*)g_M + tid);         // 0..127
        cp16(mv + 128 + tid, (const float4*)g_M + 128 + tid);   // 128..255
        if (tid < 8) cp16(mv + 256 + tid, (const float4*)g_v + tid);
        cp_commit();
    }
    stage(0);
    stage(1);

    // center-tap reference vector r_mid (also primes L2 for the ref lines)
    float rm[C_];
    #pragma unroll
    for (int c = 0; c < C_; c++)
        rm[c] = __ldg(f + ((size_t)c*HW_ + p)*S_ + (S_/2));

    // ---- wait for M|v, compute t[c] = v[c] + sum_d rm[d]*M[d][c] ----
    cp_wait<2>();          // M|v group complete (tiles 0,1 still pending)
    __syncthreads();
    float t[C_];
    {
        const float* sMv = (const float*)buf(3);
        #pragma unroll
        for (int c = 0; c < C_; c++) t[c] = sMv[1024 + c];
        #pragma unroll
        for (int d = 0; d < C_; d++) {
            float r = rm[d];
            #pragma unroll
            for (int c = 0; c < C_; c++)
                t[c] = fmaf(r, sMv[d*C_ + c], t[c]);
        }
    }
    // NOTE: buf3 is overwritten by stage(3) in iteration j=1; all threads have
    // finished reading sMv before passing iteration j=0's __syncthreads().

    float logit[S_];
    #pragma unroll
    for (int s = 0; s < S_; s++) logit[s] = 0.f;
    float refg[4][S_];

    // ---- phase 1 (unrolled so t[] indices stay static) ----
    #pragma unroll
    for (int j = 0; j < 8; j++) {
        stage(j + 2);
        cp_wait<2>();          // tile j complete
        __syncthreads();       // single sync: tile j visible, buf (j+2)%4 free
        const float* tile = (const float*)buf(j & (NBUF - 1));
        #pragma unroll
        for (int c4 = 0; c4 < 4; c4++) {
            float tc = t[4*j + c4];
            const float* row = tile + c4*TILE_F + tid*S_;
            #pragma unroll
            for (int s = 0; s < S_; s++) {
                float rv = row[s];
                logit[s] = fmaf(tc, rv, logit[s]);
                if (j == 7) refg[c4][s] = rv;   // capture ref group 7 for free
            }
        }
    }

    // ---- softmax ----
    float att[S_];
    {
        const float scale = 0.17677669529663689f;  // 1/sqrt(32)
        float mx = -1e30f;
        #pragma unroll
        for (int s = 0; s < S_; s++) { logit[s] *= scale; mx = fmaxf(mx, logit[s]); }
        float sum = 0.f;
        #pragma unroll
        for (int s = 0; s < S_; s++) { att[s] = __expf(logit[s] - mx); sum += att[s]; }
        float invs = 1.0f / sum;
        #pragma unroll
        for (int s = 0; s < S_; s++) att[s] *= invs;
    }

    // ---- phase 2 ----
    for (int j = 8; j < NTILE; j++) {
        if (j + 2 < NTILE) { stage(j + 2); cp_wait<2>(); }
        else if (j + 1 < NTILE) cp_wait<1>();
        else                    cp_wait<0>();
        __syncthreads();
        const float* tile = (const float*)buf(j & (NBUF - 1));

        int n, g;
        bool is_ref;
        if (j < 16) { n = j - 7; g = 7; is_ref = false; }
        else {
            int k2 = j - 16;
            int q  = k2 / 9;
            int r  = k2 - 9*q;
            g = 6 - q; n = r; is_ref = (r == 0);
        }
        if (is_ref) {
            #pragma unroll
            for (int c4 = 0; c4 < 4; c4++) {
                const float* row = tile + c4*TILE_F + tid*S_;
                #pragma unroll
                for (int s = 0; s < S_; s++) refg[c4][s] = row[s];
            }
        } else {
            float acc[S_];
            #pragma unroll
            for (int s = 0; s < S_; s++) acc[s] = 0.f;
            #pragma unroll
            for (int c4 = 0; c4 < 4; c4++) {
                const float* row = tile + c4*TILE_F + tid*S_;
                #pragma unroll
                for (int s = 0; s < S_; s++)
                    acc[s] = fmaf(refg[c4][s], row[s], acc[s]);
            }
            float o = 0.f;
            #pragma unroll
            for (int s = 0; s < S_; s++) o = fmaf(acc[s], att[s], o);
            out[(size_t)((n - 1)*G_ + g)*HW_ + p] = o;
        }
    }
}

extern "C" void kernel_launch(void* const* d_in, const int* in_sizes, int n_in,
                              void* d_out, int out_size) {
    const float* f  = (const float*)d_in[0];
    const float* Wp = (const float*)d_in[1];
    const float* bp = (const float*)d_in[2];

    cudaFuncSetAttribute(gcfs_main, cudaFuncAttributeMaxDynamicSharedMemorySize, SMEM_BYTES);

    gcfs_setup<<<1, 256>>>(Wp, bp);
    gcfs_main<<<HW_/PIX, NTHR, SMEM_BYTES>>>(f, (float*)d_out);
}

// round 11
// speedup vs baseline: 2.6749x; 1.0393x over previous
#include <cuda_runtime.h>
#include <cstdint>
#include <cstddef>

#define C_   32
#define H_   192
#define W_   256
#define S_   9
#define G_   8
#define HW_  (H_*W_)          // 49152
#define PIX  128              // pixels per block
#define NTHR 128
#define TILE_F  (PIX*S_)      // 1152 floats per channel sub-tile
#define TILE_F4 (TILE_F/4)    // 288 float4
#define MACRO_F4 (4*TILE_F4)  // 1152 float4 per macro tile (18432 B)
#define NBUF 4
#define SMEM_BYTES (NBUF*MACRO_F4*16)   // 73728
#define NTILE 79              // 8 phase-1 + 8 (g=7 src) + 7*9 (g=6..0)

__device__ __forceinline__ void cp16(void* smem, const void* g) {
    uint32_t sa = (uint32_t)__cvta_generic_to_shared(smem);
    asm volatile("cp.async.cg.shared.global [%0], [%1], 16;\n" :: "r"(sa), "l"(g) : "memory");
}
__device__ __forceinline__ void cp_commit() {
    asm volatile("cp.async.commit_group;\n" ::: "memory");
}
template<int NW> __device__ __forceinline__ void cp_wait() {
    asm volatile("cp.async.wait_group %0;\n" :: "n"(NW) : "memory");
}

// tile map (validated rounds 2/5):
// j in [0,8):   ref group j                 (phase 1; j==7 captures refg for g=7)
// j in [8,16):  src n=j-7, group 7
// j in [16,79): k2=j-16; q=k2/9; r=k2%9; g=6-q; r==0 -> ref group g, else src n=r group g
__device__ __forceinline__ void tdesc(int j, int& n, int& cb) {
    if (j < 8)       { n = 0;     cb = 4*j; }
    else if (j < 16) { n = j - 7; cb = 28;  }
    else {
        int k2 = j - 16;
        int q  = k2 / 9;
        int r  = k2 - 9*q;
        n  = (r == 0) ? 0 : r;
        cb = 4*(6 - q);
    }
}

__global__ __launch_bounds__(NTHR, 3)
void gcfs_main(const float* __restrict__ f,
               const float* __restrict__ Wp,
               const float* __restrict__ bp,
               float* __restrict__ out) {
    extern __shared__ float4 sbuf[];   // NBUF x MACRO_F4, dynamic (73728 B)

    const int tid  = threadIdx.x;
    const int pix0 = blockIdx.x * PIX;
    const int p    = pix0 + tid;

    auto buf = [&](int i) { return sbuf + (size_t)i * MACRO_F4; };

    auto stage = [&](int j) {
        float4* dst = buf(j & (NBUF - 1));
        int n, cb; tdesc(j, n, cb);
        #pragma unroll
        for (int k = 0; k < 9; k++) {
            int idx = tid + k*NTHR;              // 0..1151
            int sub = idx / TILE_F4;             // channel 0..3
            int off = idx - sub*TILE_F4;         // float4 within channel tile
            const float* gsrc = f + ((size_t)(n*C_ + cb + sub)*HW_ + pix0)*S_ + (size_t)off*4;
            cp16(dst + idx, gsrc);
        }
        cp_commit();
    };

    // ---- prologue ----
    // group A: Wp (256 float4) + bp (8 float4) -> buf3 (transient)
    {
        float4* mv = buf(3);
        cp16(mv + tid,       (const float4*)Wp + tid);         // 0..127
        cp16(mv + 128 + tid, (const float4*)Wp + 128 + tid);   // 128..255
        if (tid < 8) cp16(mv + 256 + tid, (const float4*)bp + tid);
        cp_commit();
    }
    // groups B,C,D: tiles 0,1,2 (keeps DRAM busy during the t-compute below)
    stage(0);
    stage(1);
    stage(2);

    // center-tap reference vector r_mid (also primes L2 for the ref lines)
    float rm[C_];
    #pragma unroll
    for (int c = 0; c < C_; c++)
        rm[c] = __ldg(f + ((size_t)c*HW_ + p)*S_ + (S_/2));

    // ---- wait for Wp|bp, compute t = Wp^T (Wp·rm + bp) ----
    cp_wait<3>();          // group A done (tiles 0,1,2 still pending)
    __syncthreads();
    float t[C_];
    {
        const float* sW = (const float*)buf(3);      // Wp row-major [e][c]
        const float* sb = sW + C_*C_;                // bp
        float q[C_];
        #pragma unroll
        for (int e = 0; e < C_; e++) {
            float acc = sb[e];
            #pragma unroll
            for (int d = 0; d < C_; d++)
                acc = fmaf(sW[e*C_ + d], rm[d], acc);
            q[e] = acc;
        }
        #pragma unroll
        for (int c = 0; c < C_; c++) t[c] = 0.f;
        #pragma unroll
        for (int e = 0; e < C_; e++) {
            float qe = q[e];
            #pragma unroll
            for (int c = 0; c < C_; c++)
                t[c] = fmaf(qe, sW[e*C_ + c], t[c]);
        }
    }
    // buf3 is first overwritten by stage(3) at j=1, which every thread issues
    // only after passing j=0's __syncthreads() -> all t-reads complete. Safe.

    float logit[S_];
    #pragma unroll
    for (int s = 0; s < S_; s++) logit[s] = 0.f;
    float refg[4][S_];

    // ---- phase 1 (unrolled so t[] indices stay static) ----
    #pragma unroll
    for (int j = 0; j < 8; j++) {
        if (j >= 1) stage(j + 2);      // tile 2 was staged in the prologue
        cp_wait<2>();                  // tile j complete
        __syncthreads();               // tile j visible; buf (j+2)&3 free
        const float* tile = (const float*)buf(j & (NBUF - 1));
        #pragma unroll
        for (int c4 = 0; c4 < 4; c4++) {
            float tc = t[4*j + c4];
            const float* row = tile + c4*TILE_F + tid*S_;
            #pragma unroll
            for (int s = 0; s < S_; s++) {
                float rv = row[s];
                logit[s] = fmaf(tc, rv, logit[s]);
                if (j == 7) refg[c4][s] = rv;   // capture ref group 7 for free
            }
        }
    }

    // ---- softmax ----
    float att[S_];
    {
        const float scale = 0.17677669529663689f;  // 1/sqrt(32)
        float mx = -1e30f;
        #pragma unroll
        for (int s = 0; s < S_; s++) { logit[s] *= scale; mx = fmaxf(mx, logit[s]); }
        float sum = 0.f;
        #pragma unroll
        for (int s = 0; s < S_; s++) { att[s] = __expf(logit[s] - mx); sum += att[s]; }
        float invs = 1.0f / sum;
        #pragma unroll
        for (int s = 0; s < S_; s++) att[s] *= invs;
    }

    // ---- phase 2 ----
    for (int j = 8; j < NTILE; j++) {
        if (j + 2 < NTILE) { stage(j + 2); cp_wait<2>(); }
        else if (j + 1 < NTILE) cp_wait<1>();
        else                    cp_wait<0>();
        __syncthreads();
        const float* tile = (const float*)buf(j & (NBUF - 1));

        int n, g;
        bool is_ref;
        if (j < 16) { n = j - 7; g = 7; is_ref = false; }
        else {
            int k2 = j - 16;
            int q2 = k2 / 9;
            int r  = k2 - 9*q2;
            g = 6 - q2; n = r; is_ref = (r == 0);
        }
        if (is_ref) {
            #pragma unroll
            for (int c4 = 0; c4 < 4; c4++) {
                const float* row = tile + c4*TILE_F + tid*S_;
                #pragma unroll
                for (int s = 0; s < S_; s++) refg[c4][s] = row[s];
            }
        } else {
            float acc[S_];
            #pragma unroll
            for (int s = 0; s < S_; s++) acc[s] = 0.f;
            #pragma unroll
            for (int c4 = 0; c4 < 4; c4++) {
                const float* row = tile + c4*TILE_F + tid*S_;
                #pragma unroll
                for (int s = 0; s < S_; s++)
                    acc[s] = fmaf(refg[c4][s], row[s], acc[s]);
            }
            float o = 0.f;
            #pragma unroll
            for (int s = 0; s < S_; s++) o = fmaf(acc[s], att[s], o);
            out[(size_t)((n - 1)*G_ + g)*HW_ + p] = o;
        }
    }
}

extern "C" void kernel_launch(void* const* d_in, const int* in_sizes, int n_in,
                              void* d_out, int out_size) {
    const float* f  = (const float*)d_in[0];
    const float* Wp = (const float*)d_in[1];
    const float* bp = (const float*)d_in[2];

    cudaFuncSetAttribute(gcfs_main, cudaFuncAttributeMaxDynamicSharedMemorySize, SMEM_BYTES);
    gcfs_main<<<HW_/PIX, NTHR, SMEM_BYTES>>>(f, Wp, bp, (float*)d_out);
}